// round 10
// baseline (speedup 1.0000x reference)
#include <cuda_runtime.h>
#include <cuda_bf16.h>
#include <cuda_fp8.h>
#include <cstdint>
#include <cstddef>

#define MM 8192
#define NN 4096
#define KK 4096
#define KC 64                      // k elements per chunk (=128B per row)
#define NKC (KK / KC)              // 64 chunks
#define SM_STRIDE 144              // padded smem row stride (bytes): 16B-aligned, conflict-free
#define ASTAGE (128 * SM_STRIDE)
#define BSTAGE (128 * SM_STRIDE)
#define STAGE_BYTES (ASTAGE + BSTAGE)
#define NSTAGES 3
#define GEMM_SMEM (1024 + NSTAGES * STAGE_BYTES)

// quantized values stored exactly as bf16 (e4m3 subset of bf16), plain row-major
__device__ __align__(256) uint16_t g_Aq[(size_t)MM * KK];  // 64MB
__device__ __align__(256) uint16_t g_Bq[(size_t)NN * KK];  // 32MB
__device__ float g_Xs[MM];
__device__ float g_Ws[NN];

// ---------------- helpers ----------------
__device__ __forceinline__ uint16_t fp8q(float t, float sc) {
    __nv_fp8_e4m3 q(t / sc);            // RN satfinite: matches jnp astype(float8_e4m3fn)
    return __bfloat16_as_ushort(__float2bfloat16(float(q)));  // exact
}
__device__ __forceinline__ uint32_t smem_u32(const void* p) {
    uint32_t a;
    asm("{ .reg .u64 t; cvta.to.shared.u64 t, %1; cvt.u32.u64 %0, t; }" : "=r"(a) : "l"(p));
    return a;
}
__device__ __forceinline__ void cp_async16(uint32_t dst, const void* src) {
    asm volatile("cp.async.cg.shared.global [%0], [%1], 16;" :: "r"(dst), "l"(src) : "memory");
}
__device__ __forceinline__ void cp_commit() {
    asm volatile("cp.async.commit_group;" ::: "memory");
}
template <int N>
__device__ __forceinline__ void cp_wait() {
    asm volatile("cp.async.wait_group %0;" :: "n"(N) : "memory");
}
#define LDSM_X4(r, a) \
    asm volatile("ldmatrix.sync.aligned.m8n8.x4.shared.b16 {%0, %1, %2, %3}, [%4];" \
        : "=r"((r)[0]), "=r"((r)[1]), "=r"((r)[2]), "=r"((r)[3]) : "r"(a))
__device__ __forceinline__ void mma16816(float* d, const uint32_t* a, uint32_t b0, uint32_t b1) {
    asm volatile(
        "mma.sync.aligned.m16n8k16.row.col.f32.bf16.bf16.f32 "
        "{%0, %1, %2, %3}, {%4, %5, %6, %7}, {%8, %9}, {%0, %1, %2, %3};"
        : "+f"(d[0]), "+f"(d[1]), "+f"(d[2]), "+f"(d[3])
        : "r"(a[0]), "r"(a[1]), "r"(a[2]), "r"(a[3]), "r"(b0), "r"(b1));
}
// round to bf16 (matching jnp astype) then widen to f32 — output buffer is FLOAT32
__device__ __forceinline__ float bf16r(float v) {
    return __bfloat162float(__float2bfloat16(v));
}

// ---------------- W prep: rowwise fp8 quant -> plain row-major bf16 ----------------
__global__ void __launch_bounds__(128) wprep_kernel(const float* __restrict__ W) {
    const int row = blockIdx.x, tid = threadIdx.x;
    const float4* wr = reinterpret_cast<const float4*>(W + (size_t)row * KK);
    float4 v[8];
    float rmax = 0.f;
#pragma unroll
    for (int i = 0; i < 8; i++) {
        v[i] = wr[i * 128 + tid];
        rmax = fmaxf(rmax, fmaxf(fmaxf(fabsf(v[i].x), fabsf(v[i].y)),
                                 fmaxf(fabsf(v[i].z), fabsf(v[i].w))));
    }
#pragma unroll
    for (int o = 16; o > 0; o >>= 1) rmax = fmaxf(rmax, __shfl_xor_sync(0xffffffffu, rmax, o));
    __shared__ float sred[4]; __shared__ float sscale;
    if ((tid & 31) == 0) sred[tid >> 5] = rmax;
    __syncthreads();
    if (tid == 0) {
        float mx = fmaxf(fmaxf(sred[0], sred[1]), fmaxf(sred[2], sred[3]));
        float sc = fmaxf(mx, 1e-12f) / 448.0f;
        sscale = sc; g_Ws[row] = sc;
    }
    __syncthreads();
    const float sc = sscale;
#pragma unroll
    for (int i = 0; i < 8; i++) {
        int k0 = (i * 128 + tid) * 4;
        ushort4 pk;
        pk.x = fp8q(v[i].x, sc);
        pk.y = fp8q(v[i].y, sc);
        pk.z = fp8q(v[i].z, sc);
        pk.w = fp8q(v[i].w, sc);
        *reinterpret_cast<ushort4*>(g_Bq + (size_t)row * KK + k0) = pk;
    }
}

// ---------------- X prep: srelu -> 2:4 top-2 (stable) -> rowwise fp8 quant ----------------
__global__ void __launch_bounds__(128) xprep_kernel(const float* __restrict__ x) {
    const int row = blockIdx.x, tid = threadIdx.x;
    const float4* xr = reinterpret_cast<const float4*>(x + (size_t)row * KK);
    float v[8][4];
    float rmax = 0.f;
#pragma unroll
    for (int i = 0; i < 8; i++) {
        float4 p = xr[i * 128 + tid];
        float s0 = p.x > 0.f ? p.x * p.x : 0.f;
        float s1 = p.y > 0.f ? p.y * p.y : 0.f;
        float s2 = p.z > 0.f ? p.z * p.z : 0.f;
        float s3 = p.w > 0.f ? p.w * p.w : 0.f;
        // stable descending rank: ties keep lower index (matches lax.top_k)
        int r0 = (s1 >  s0) + (s2 >  s0) + (s3 >  s0);
        int r1 = (s0 >= s1) + (s2 >  s1) + (s3 >  s1);
        int r2 = (s0 >= s2) + (s1 >= s2) + (s3 >  s2);
        int r3 = (s0 >= s3) + (s1 >= s3) + (s2 >= s3);
        v[i][0] = r0 < 2 ? s0 : 0.f;
        v[i][1] = r1 < 2 ? s1 : 0.f;
        v[i][2] = r2 < 2 ? s2 : 0.f;
        v[i][3] = r3 < 2 ? s3 : 0.f;
        rmax = fmaxf(rmax, fmaxf(fmaxf(s0, s1), fmaxf(s2, s3))); // row max survives 2:4
    }
#pragma unroll
    for (int o = 16; o > 0; o >>= 1) rmax = fmaxf(rmax, __shfl_xor_sync(0xffffffffu, rmax, o));
    __shared__ float sred[4]; __shared__ float sscale;
    if ((tid & 31) == 0) sred[tid >> 5] = rmax;
    __syncthreads();
    if (tid == 0) {
        float mx = fmaxf(fmaxf(sred[0], sred[1]), fmaxf(sred[2], sred[3]));
        float sc = fmaxf(mx, 1e-12f) / 448.0f;
        sscale = sc; g_Xs[row] = sc;
    }
    __syncthreads();
    const float sc = sscale;
#pragma unroll
    for (int i = 0; i < 8; i++) {
        int k0 = (i * 128 + tid) * 4;
        ushort4 pk;
        pk.x = fp8q(v[i][0], sc);
        pk.y = fp8q(v[i][1], sc);
        pk.z = fp8q(v[i][2], sc);
        pk.w = fp8q(v[i][3], sc);
        *reinterpret_cast<ushort4*>(g_Aq + (size_t)row * KK + k0) = pk;
    }
}

// ---------------- GEMM: 128x128 CTA tile, 256 threads, mma.sync bf16, padded smem ----------------
__global__ void __launch_bounds__(256, 1) gemm_kernel(float* __restrict__ out) {
    extern __shared__ uint8_t dynsm[];
    uint8_t* base = (uint8_t*)(((uintptr_t)dynsm + 1023) & ~(uintptr_t)1023);
    const uint32_t sbase = smem_u32(base);
    const int tid = threadIdx.x, wid = tid >> 5, lane = tid & 31;
    const int mt = blockIdx.x >> 5, nt = blockIdx.x & 31;
    const int m0 = mt * 128, n0g = nt * 128;

    const int wm = wid & 3, wn = wid >> 2;   // warp tile: 32(M) x 64(N)

    float acc[2][8][4];
#pragma unroll
    for (int i = 0; i < 2; i++)
#pragma unroll
        for (int j = 0; j < 8; j++)
#pragma unroll
            for (int k = 0; k < 4; k++) acc[i][j][k] = 0.f;

    const int crow = tid >> 1;              // 0..127
    const int coff = (tid & 1) * 64;        // 0 or 64 bytes
    auto copy_stage = [&](int s, int c) {
        uint32_t sa = sbase + s * STAGE_BYTES + crow * SM_STRIDE + coff;
        uint32_t sb = sa + ASTAGE;
        const uint8_t* ga = (const uint8_t*)(g_Aq + (size_t)(m0 + crow) * KK + c * KC) + coff;
        const uint8_t* gb = (const uint8_t*)(g_Bq + (size_t)(n0g + crow) * KK + c * KC) + coff;
#pragma unroll
        for (int i = 0; i < 4; i++) cp_async16(sa + i * 16, ga + i * 16);
#pragma unroll
        for (int i = 0; i < 4; i++) cp_async16(sb + i * 16, gb + i * 16);
        cp_commit();
    };

    copy_stage(0, 0); copy_stage(1, 1);

    const int lr = lane & 15;          // ldmatrix row within 16
    const int lc8 = (lane >> 4) & 1;   // +8 k elements (16B) for lanes 16-31

    int s = 0;
    for (int c = 0; c < NKC; c++) {
        if (c + 2 < NKC) copy_stage((s + 2) % NSTAGES, c + 2);
        const int rem = NKC - 1 - c;
        if (rem >= 2) cp_wait<2>();
        else if (rem == 1) cp_wait<1>();
        else cp_wait<0>();
        __syncthreads();

        const uint32_t abase = sbase + s * STAGE_BYTES;
        const uint32_t bbase = abase + ASTAGE;
#pragma unroll
        for (int ks = 0; ks < 4; ks++) {
            const uint32_t kb = ks * 32 + lc8 * 16;   // byte offset in row
            uint32_t a[2][4];
#pragma unroll
            for (int mi = 0; mi < 2; mi++) {
                int row = wm * 32 + mi * 16 + lr;
                LDSM_X4(a[mi], abase + row * SM_STRIDE + kb);
            }
            uint32_t b[4][4];
#pragma unroll
            for (int nb = 0; nb < 4; nb++) {
                int row = wn * 64 + nb * 16 + lr;
                LDSM_X4(b[nb], bbase + row * SM_STRIDE + kb);
            }
#pragma unroll
            for (int mi = 0; mi < 2; mi++)
#pragma unroll
                for (int nb = 0; nb < 4; nb++) {
                    mma16816(acc[mi][2 * nb + 0], a[mi], b[nb][0], b[nb][2]);
                    mma16816(acc[mi][2 * nb + 1], a[mi], b[nb][1], b[nb][3]);
                }
        }
        __syncthreads();
        s = (s + 1) % NSTAGES;
    }

    // epilogue: apply Xs[m] * Ws[n], round to bf16, store as FLOAT32 (output dtype is f32)
    const int wm0 = m0 + wm * 32;
    const int wn0 = n0g + wn * 64;
#pragma unroll
    for (int mi = 0; mi < 2; mi++) {
#pragma unroll
        for (int half = 0; half < 2; half++) {
            int r = wm0 + mi * 16 + (lane >> 2) + half * 8;
            float xs = __ldg(&g_Xs[r]);
            float* orow = out + (size_t)r * NN;
#pragma unroll
            for (int nb8 = 0; nb8 < 8; nb8++) {
                int n = wn0 + nb8 * 8 + (lane & 3) * 2;
                float w0 = __ldg(&g_Ws[n]), w1 = __ldg(&g_Ws[n + 1]);
                float2 o;
                o.x = bf16r(acc[mi][nb8][half * 2 + 0] * xs * w0);
                o.y = bf16r(acc[mi][nb8][half * 2 + 1] * xs * w1);
                *reinterpret_cast<float2*>(orow + n) = o;
            }
        }
    }
}

extern "C" void kernel_launch(void* const* d_in, const int* in_sizes, int n_in,
                              void* d_out, int out_size) {
    // Select inputs by element count — robust to metadata ordering.
    // x: 8192*4096 = 33554432, W: 4096*4096 = 16777216.
    const float* x = (const float*)d_in[0];
    const float* W = (const float*)d_in[1];
    if (n_in >= 2 && in_sizes[0] == NN * KK && in_sizes[1] == MM * KK) {
        x = (const float*)d_in[1];
        W = (const float*)d_in[0];
    }
    float* out = (float*)d_out;     // __output__ dtype is float32 (bf16 upcast by harness)
    (void)out_size;

    cudaFuncSetAttribute(gemm_kernel, cudaFuncAttributeMaxDynamicSharedMemorySize, GEMM_SMEM);

    wprep_kernel<<<NN, 128>>>(W);
    xprep_kernel<<<MM, 128>>>(x);
    gemm_kernel<<<(MM / 128) * (NN / 128), 256, GEMM_SMEM>>>(out);
}

// round 11
// speedup vs baseline: 1.0776x; 1.0776x over previous
#include <cuda_runtime.h>
#include <cuda_bf16.h>
#include <cuda_fp8.h>
#include <cstdint>
#include <cstddef>

#define MM 8192
#define NN 4096
#define KK 4096
#define KC 128                     // k elements (fp8 bytes) per chunk = 128B per row
#define NKC (KK / KC)              // 32 chunks
#define SM_STRIDE 144              // padded smem row stride (bytes): 16B-aligned, conflict-free
#define ASTAGE (128 * SM_STRIDE)
#define BSTAGE (128 * SM_STRIDE)
#define STAGE_BYTES (ASTAGE + BSTAGE)
#define NSTAGES 3
#define GEMM_SMEM (1024 + NSTAGES * STAGE_BYTES)

// fp8 e4m3 images, plain row-major (operand bytes identical to reference quantization)
__device__ __align__(256) uint8_t g_Aq[(size_t)MM * KK];  // 32MB
__device__ __align__(256) uint8_t g_Bq[(size_t)NN * KK];  // 16MB
__device__ float g_Xs[MM];
__device__ float g_Ws[NN];

// ---------------- helpers ----------------
__device__ __forceinline__ uint8_t fp8b(float t, float sc) {
    __nv_fp8_e4m3 q(t / sc);            // RN satfinite: matches jnp astype(float8_e4m3fn)
    return q.__x;
}
__device__ __forceinline__ uint32_t smem_u32(const void* p) {
    uint32_t a;
    asm("{ .reg .u64 t; cvta.to.shared.u64 t, %1; cvt.u32.u64 %0, t; }" : "=r"(a) : "l"(p));
    return a;
}
__device__ __forceinline__ void cp_async16(uint32_t dst, const void* src) {
    asm volatile("cp.async.cg.shared.global [%0], [%1], 16;" :: "r"(dst), "l"(src) : "memory");
}
__device__ __forceinline__ void cp_commit() {
    asm volatile("cp.async.commit_group;" ::: "memory");
}
template <int N>
__device__ __forceinline__ void cp_wait() {
    asm volatile("cp.async.wait_group %0;" :: "n"(N) : "memory");
}
#define LDSM_X4(r, a) \
    asm volatile("ldmatrix.sync.aligned.m8n8.x4.shared.b16 {%0, %1, %2, %3}, [%4];" \
        : "=r"((r)[0]), "=r"((r)[1]), "=r"((r)[2]), "=r"((r)[3]) : "r"(a))
// fp8 dense mma: D[16x8] += A[16x32] * B[32x8], e4m3 inputs, f32 accum
__device__ __forceinline__ void mma16832(float* d, const uint32_t* a, uint32_t b0, uint32_t b1) {
    asm volatile(
        "mma.sync.aligned.m16n8k32.row.col.f32.e4m3.e4m3.f32 "
        "{%0, %1, %2, %3}, {%4, %5, %6, %7}, {%8, %9}, {%0, %1, %2, %3};"
        : "+f"(d[0]), "+f"(d[1]), "+f"(d[2]), "+f"(d[3])
        : "r"(a[0]), "r"(a[1]), "r"(a[2]), "r"(a[3]), "r"(b0), "r"(b1));
}
// round to bf16 (matching jnp astype) then widen to f32 — output buffer is FLOAT32
__device__ __forceinline__ float bf16r(float v) {
    return __bfloat162float(__float2bfloat16(v));
}

// ---------------- W prep: rowwise fp8 quant -> row-major e4m3 bytes ----------------
__global__ void __launch_bounds__(128) wprep_kernel(const float* __restrict__ W) {
    const int row = blockIdx.x, tid = threadIdx.x;
    const float4* wr = reinterpret_cast<const float4*>(W + (size_t)row * KK);
    float4 v[8];
    float rmax = 0.f;
#pragma unroll
    for (int i = 0; i < 8; i++) {
        v[i] = wr[i * 128 + tid];
        rmax = fmaxf(rmax, fmaxf(fmaxf(fabsf(v[i].x), fabsf(v[i].y)),
                                 fmaxf(fabsf(v[i].z), fabsf(v[i].w))));
    }
#pragma unroll
    for (int o = 16; o > 0; o >>= 1) rmax = fmaxf(rmax, __shfl_xor_sync(0xffffffffu, rmax, o));
    __shared__ float sred[4]; __shared__ float sscale;
    if ((tid & 31) == 0) sred[tid >> 5] = rmax;
    __syncthreads();
    if (tid == 0) {
        float mx = fmaxf(fmaxf(sred[0], sred[1]), fmaxf(sred[2], sred[3]));
        float sc = fmaxf(mx, 1e-12f) / 448.0f;
        sscale = sc; g_Ws[row] = sc;
    }
    __syncthreads();
    const float sc = sscale;
#pragma unroll
    for (int i = 0; i < 8; i++) {
        int k0 = (i * 128 + tid) * 4;
        uchar4 pk;
        pk.x = fp8b(v[i].x, sc);
        pk.y = fp8b(v[i].y, sc);
        pk.z = fp8b(v[i].z, sc);
        pk.w = fp8b(v[i].w, sc);
        *reinterpret_cast<uchar4*>(g_Bq + (size_t)row * KK + k0) = pk;
    }
}

// ---------------- X prep: srelu -> 2:4 top-2 (stable) -> rowwise fp8 quant ----------------
__global__ void __launch_bounds__(128) xprep_kernel(const float* __restrict__ x) {
    const int row = blockIdx.x, tid = threadIdx.x;
    const float4* xr = reinterpret_cast<const float4*>(x + (size_t)row * KK);
    float v[8][4];
    float rmax = 0.f;
#pragma unroll
    for (int i = 0; i < 8; i++) {
        float4 p = xr[i * 128 + tid];
        float s0 = p.x > 0.f ? p.x * p.x : 0.f;
        float s1 = p.y > 0.f ? p.y * p.y : 0.f;
        float s2 = p.z > 0.f ? p.z * p.z : 0.f;
        float s3 = p.w > 0.f ? p.w * p.w : 0.f;
        // stable descending rank: ties keep lower index (matches lax.top_k)
        int r0 = (s1 >  s0) + (s2 >  s0) + (s3 >  s0);
        int r1 = (s0 >= s1) + (s2 >  s1) + (s3 >  s1);
        int r2 = (s0 >= s2) + (s1 >= s2) + (s3 >  s2);
        int r3 = (s0 >= s3) + (s1 >= s3) + (s2 >= s3);
        v[i][0] = r0 < 2 ? s0 : 0.f;
        v[i][1] = r1 < 2 ? s1 : 0.f;
        v[i][2] = r2 < 2 ? s2 : 0.f;
        v[i][3] = r3 < 2 ? s3 : 0.f;
        rmax = fmaxf(rmax, fmaxf(fmaxf(s0, s1), fmaxf(s2, s3))); // row max survives 2:4
    }
#pragma unroll
    for (int o = 16; o > 0; o >>= 1) rmax = fmaxf(rmax, __shfl_xor_sync(0xffffffffu, rmax, o));
    __shared__ float sred[4]; __shared__ float sscale;
    if ((tid & 31) == 0) sred[tid >> 5] = rmax;
    __syncthreads();
    if (tid == 0) {
        float mx = fmaxf(fmaxf(sred[0], sred[1]), fmaxf(sred[2], sred[3]));
        float sc = fmaxf(mx, 1e-12f) / 448.0f;
        sscale = sc; g_Xs[row] = sc;
    }
    __syncthreads();
    const float sc = sscale;
#pragma unroll
    for (int i = 0; i < 8; i++) {
        int k0 = (i * 128 + tid) * 4;
        uchar4 pk;
        pk.x = fp8b(v[i][0], sc);
        pk.y = fp8b(v[i][1], sc);
        pk.z = fp8b(v[i][2], sc);
        pk.w = fp8b(v[i][3], sc);
        *reinterpret_cast<uchar4*>(g_Aq + (size_t)row * KK + k0) = pk;
    }
}

// ---------------- GEMM: 128x128 CTA tile, 256 threads, fp8 mma.sync, padded smem ----------------
__global__ void __launch_bounds__(256, 1) gemm_kernel(float* __restrict__ out) {
    extern __shared__ uint8_t dynsm[];
    uint8_t* base = (uint8_t*)(((uintptr_t)dynsm + 1023) & ~(uintptr_t)1023);
    const uint32_t sbase = smem_u32(base);
    const int tid = threadIdx.x, wid = tid >> 5, lane = tid & 31;
    const int mt = blockIdx.x >> 5, nt = blockIdx.x & 31;
    const int m0 = mt * 128, n0g = nt * 128;

    const int wm = wid & 3, wn = wid >> 2;   // warp tile: 32(M) x 64(N)

    float acc[2][8][4];
#pragma unroll
    for (int i = 0; i < 2; i++)
#pragma unroll
        for (int j = 0; j < 8; j++)
#pragma unroll
            for (int k = 0; k < 4; k++) acc[i][j][k] = 0.f;

    // copy chunk: 128 rows x 128 fp8 bytes for A and B (2 threads/row x 64B)
    const int crow = tid >> 1;              // 0..127
    const int coff = (tid & 1) * 64;        // 0 or 64 bytes
    auto copy_stage = [&](int s, int c) {
        uint32_t sa = sbase + s * STAGE_BYTES + crow * SM_STRIDE + coff;
        uint32_t sb = sa + ASTAGE;
        const uint8_t* ga = g_Aq + (size_t)(m0 + crow) * KK + c * KC + coff;
        const uint8_t* gb = g_Bq + (size_t)(n0g + crow) * KK + c * KC + coff;
#pragma unroll
        for (int i = 0; i < 4; i++) cp_async16(sa + i * 16, ga + i * 16);
#pragma unroll
        for (int i = 0; i < 4; i++) cp_async16(sb + i * 16, gb + i * 16);
        cp_commit();
    };

    copy_stage(0, 0); copy_stage(1, 1);

    const int lr = lane & 15;          // fragment row within 16
    const int lc8 = (lane >> 4) & 1;   // +16B (16 k-bytes) for lanes 16-31

    int s = 0;
    for (int c = 0; c < NKC; c++) {
        if (c + 2 < NKC) copy_stage((s + 2) % NSTAGES, c + 2);
        const int rem = NKC - 1 - c;
        if (rem >= 2) cp_wait<2>();
        else if (rem == 1) cp_wait<1>();
        else cp_wait<0>();
        __syncthreads();

        const uint32_t abase = sbase + s * STAGE_BYTES;
        const uint32_t bbase = abase + ASTAGE;
#pragma unroll
        for (int ks = 0; ks < 4; ks++) {
            const uint32_t kb = ks * 32 + lc8 * 16;   // byte offset in 128B row
            uint32_t a[2][4];
#pragma unroll
            for (int mi = 0; mi < 2; mi++) {
                int row = wm * 32 + mi * 16 + lr;
                LDSM_X4(a[mi], abase + row * SM_STRIDE + kb);
            }
            uint32_t b[4][4];
#pragma unroll
            for (int nb = 0; nb < 4; nb++) {
                int row = wn * 64 + nb * 16 + lr;
                LDSM_X4(b[nb], bbase + row * SM_STRIDE + kb);
            }
#pragma unroll
            for (int mi = 0; mi < 2; mi++)
#pragma unroll
                for (int nb = 0; nb < 4; nb++) {
                    mma16832(acc[mi][2 * nb + 0], a[mi], b[nb][0], b[nb][2]);
                    mma16832(acc[mi][2 * nb + 1], a[mi], b[nb][1], b[nb][3]);
                }
        }
        __syncthreads();
        s = (s + 1) % NSTAGES;
    }

    // epilogue: apply Xs[m] * Ws[n], round to bf16, store as FLOAT32
    const int wm0 = m0 + wm * 32;
    const int wn0 = n0g + wn * 64;
#pragma unroll
    for (int mi = 0; mi < 2; mi++) {
#pragma unroll
        for (int half = 0; half < 2; half++) {
            int r = wm0 + mi * 16 + (lane >> 2) + half * 8;
            float xs = __ldg(&g_Xs[r]);
            float* orow = out + (size_t)r * NN;
#pragma unroll
            for (int nb8 = 0; nb8 < 8; nb8++) {
                int n = wn0 + nb8 * 8 + (lane & 3) * 2;
                float w0 = __ldg(&g_Ws[n]), w1 = __ldg(&g_Ws[n + 1]);
                float2 o;
                o.x = bf16r(acc[mi][nb8][half * 2 + 0] * xs * w0);
                o.y = bf16r(acc[mi][nb8][half * 2 + 1] * xs * w1);
                *reinterpret_cast<float2*>(orow + n) = o;
            }
        }
    }
}

extern "C" void kernel_launch(void* const* d_in, const int* in_sizes, int n_in,
                              void* d_out, int out_size) {
    // Select inputs by element count — robust to metadata ordering.
    const float* x = (const float*)d_in[0];
    const float* W = (const float*)d_in[1];
    if (n_in >= 2 && in_sizes[0] == NN * KK && in_sizes[1] == MM * KK) {
        x = (const float*)d_in[1];
        W = (const float*)d_in[0];
    }
    float* out = (float*)d_out;     // __output__ dtype is float32
    (void)out_size;

    cudaFuncSetAttribute(gemm_kernel, cudaFuncAttributeMaxDynamicSharedMemorySize, GEMM_SMEM);

    wprep_kernel<<<NN, 128>>>(W);
    xprep_kernel<<<MM, 128>>>(x);
    gemm_kernel<<<(MM / 128) * (NN / 128), 256, GEMM_SMEM>>>(out);
}

// round 14
// speedup vs baseline: 1.1575x; 1.0742x over previous
#include <cuda_runtime.h>
#include <cuda_bf16.h>
#include <cuda_fp8.h>
#include <cstdint>
#include <cstddef>

#define MM 8192
#define NN 4096
#define KK 4096
#define KC 64                      // logical k per pipeline stage
#define NKC (KK / KC)              // 64 stages
#define A_STRIDE 80                // compressed A smem row stride (64B data + pad)
#define B_STRIDE 144               // B smem row stride (128B data + pad)
#define SMA (128 * A_STRIDE)       // 10240
#define SMMETA 2048                // 8 rb x 2 k32 x 32 words x 4B
#define SMB (128 * B_STRIDE)       // 18432
#define STAGE_BYTES (SMA + SMMETA + SMB)   // 30720
#define NSTAGES 3
#define GEMM_SMEM (1024 + NSTAGES * STAGE_BYTES)

// A: 2:4-compressed quantized values as bf16 (2 per group, 4B) -> KK bytes/row
__device__ __align__(256) uint8_t g_Aqs[(size_t)MM * KK];                     // 32MB
// metadata: [rb(512)][k32 chunk(128)][32 words x 4B]
__device__ __align__(256) uint8_t g_Am[(size_t)(MM / 16) * (KK / 32) * 128];  // 8MB
// B: dense quantized values as bf16, row-major
__device__ __align__(256) uint16_t g_Bq[(size_t)NN * KK];                     // 32MB
__device__ float g_Xs[MM];
__device__ float g_Ws[NN];

// ---------------- helpers ----------------
__device__ __forceinline__ uint16_t q2bf(float t, float sc) {
    __nv_fp8_e4m3 q(t / sc);            // RN satfinite: matches jnp astype(float8_e4m3fn)
    return __bfloat16_as_ushort(__float2bfloat16(float(q)));  // exact (e4m3 subset of bf16)
}
__device__ __forceinline__ uint32_t smem_u32(const void* p) {
    uint32_t a;
    asm("{ .reg .u64 t; cvta.to.shared.u64 t, %1; cvt.u32.u64 %0, t; }" : "=r"(a) : "l"(p));
    return a;
}
__device__ __forceinline__ void cp_async16(uint32_t dst, const void* src) {
    asm volatile("cp.async.cg.shared.global [%0], [%1], 16;" :: "r"(dst), "l"(src) : "memory");
}
__device__ __forceinline__ void cp_async8(uint32_t dst, const void* src) {
    asm volatile("cp.async.ca.shared.global [%0], [%1], 8;" :: "r"(dst), "l"(src) : "memory");
}
__device__ __forceinline__ void cp_commit() {
    asm volatile("cp.async.commit_group;" ::: "memory");
}
template <int N>
__device__ __forceinline__ void cp_wait() {
    asm volatile("cp.async.wait_group %0;" :: "n"(N) : "memory");
}
#define LDSM_X4(r, a) \
    asm volatile("ldmatrix.sync.aligned.m8n8.x4.shared.b16 {%0, %1, %2, %3}, [%4];" \
        : "=r"((r)[0]), "=r"((r)[1]), "=r"((r)[2]), "=r"((r)[3]) : "r"(a))
// 2:4 sparse bf16 mma: D[16x8] += A[16x32 sparse] * B[32x8], f32 accum, selector 0
__device__ __forceinline__ void mma_sp(float* d, const uint32_t* a,
                                       uint32_t b0, uint32_t b1, uint32_t b2, uint32_t b3,
                                       uint32_t e) {
    asm volatile(
        "mma.sp::ordered_metadata.sync.aligned.m16n8k32.row.col.f32.bf16.bf16.f32 "
        "{%0, %1, %2, %3}, {%4, %5, %6, %7}, {%8, %9, %10, %11}, {%0, %1, %2, %3}, %12, 0x0;"
        : "+f"(d[0]), "+f"(d[1]), "+f"(d[2]), "+f"(d[3])
        : "r"(a[0]), "r"(a[1]), "r"(a[2]), "r"(a[3]),
          "r"(b0), "r"(b1), "r"(b2), "r"(b3), "r"(e));
}
__device__ __forceinline__ float bf16r(float v) {
    return __bfloat162float(__float2bfloat16(v));   // output f32 holds bf16-rounded values
}

// ---------------- W prep: rowwise fp8 quant -> row-major bf16 values ----------------
__global__ void __launch_bounds__(128) wprep_kernel(const float* __restrict__ W) {
    const int row = blockIdx.x, tid = threadIdx.x;
    const float4* wr = reinterpret_cast<const float4*>(W + (size_t)row * KK);
    float4 v[8];
    float rmax = 0.f;
#pragma unroll
    for (int i = 0; i < 8; i++) {
        v[i] = wr[i * 128 + tid];
        rmax = fmaxf(rmax, fmaxf(fmaxf(fabsf(v[i].x), fabsf(v[i].y)),
                                 fmaxf(fabsf(v[i].z), fabsf(v[i].w))));
    }
#pragma unroll
    for (int o = 16; o > 0; o >>= 1) rmax = fmaxf(rmax, __shfl_xor_sync(0xffffffffu, rmax, o));
    __shared__ float sred[4]; __shared__ float sscale;
    if ((tid & 31) == 0) sred[tid >> 5] = rmax;
    __syncthreads();
    if (tid == 0) {
        float mx = fmaxf(fmaxf(sred[0], sred[1]), fmaxf(sred[2], sred[3]));
        float sc = fmaxf(mx, 1e-12f) / 448.0f;
        sscale = sc; g_Ws[row] = sc;
    }
    __syncthreads();
    const float sc = sscale;
#pragma unroll
    for (int i = 0; i < 8; i++) {
        int k0 = (i * 128 + tid) * 4;
        ushort4 pk;
        pk.x = q2bf(v[i].x, sc);
        pk.y = q2bf(v[i].y, sc);
        pk.z = q2bf(v[i].z, sc);
        pk.w = q2bf(v[i].w, sc);
        *reinterpret_cast<ushort4*>(g_Bq + (size_t)row * KK + k0) = pk;
    }
}

// ---------------- X prep: srelu -> 2:4 top-2 -> fp8 quant -> compressed bf16 A + metadata ----------------
__global__ void __launch_bounds__(128) xprep_kernel(const float* __restrict__ x) {
    const int row = blockIdx.x, tid = threadIdx.x;
    const float4* xr = reinterpret_cast<const float4*>(x + (size_t)row * KK);
    float v[8][4];
    uint8_t nib[8];
    float rmax = 0.f;
    __shared__ uint8_t nibs[1024];
    __shared__ float sred[4]; __shared__ float sscale;
#pragma unroll
    for (int i = 0; i < 8; i++) {
        float4 p = xr[i * 128 + tid];
        float s0 = p.x > 0.f ? p.x * p.x : 0.f;
        float s1 = p.y > 0.f ? p.y * p.y : 0.f;
        float s2 = p.z > 0.f ? p.z * p.z : 0.f;
        float s3 = p.w > 0.f ? p.w * p.w : 0.f;
        // stable descending rank: ties keep lower index (matches lax.top_k)
        int r0 = (s1 >  s0) + (s2 >  s0) + (s3 >  s0);
        int r1 = (s0 >= s1) + (s2 >  s1) + (s3 >  s1);
        int r2 = (s0 >= s2) + (s1 >= s2) + (s3 >  s2);
        int r3 = (s0 >= s3) + (s1 >= s3) + (s2 >= s3);
        // kept positions (exactly 2), ascending order
        int p0 = (r0 < 2) ? 0 : ((r1 < 2) ? 1 : 2);
        int p1 = (r3 < 2) ? 3 : ((r2 < 2) ? 2 : 1);
        nib[i] = (uint8_t)(p0 | (p1 << 2));
        v[i][0] = s0; v[i][1] = s1; v[i][2] = s2; v[i][3] = s3;
        rmax = fmaxf(rmax, fmaxf(fmaxf(s0, s1), fmaxf(s2, s3))); // row max always kept by 2:4
        nibs[i * 128 + tid] = nib[i];
    }
#pragma unroll
    for (int o = 16; o > 0; o >>= 1) rmax = fmaxf(rmax, __shfl_xor_sync(0xffffffffu, rmax, o));
    if ((tid & 31) == 0) sred[tid >> 5] = rmax;
    __syncthreads();
    if (tid == 0) {
        float mx = fmaxf(fmaxf(sred[0], sred[1]), fmaxf(sred[2], sred[3]));
        float sc = fmaxf(mx, 1e-12f) / 448.0f;
        sscale = sc; g_Xs[row] = sc;
    }
    __syncthreads();
    const float sc = sscale;
    // compressed values: 2 kept quantized bf16 per group (4 bytes), ascending k
#pragma unroll
    for (int i = 0; i < 8; i++) {
        int gi = i * 128 + tid;                 // group index in row (0..1023)
        int p0 = nib[i] & 3, p1 = nib[i] >> 2;
        uint32_t pk = (uint32_t)q2bf(v[i][p0], sc) | ((uint32_t)q2bf(v[i][p1], sc) << 16);
        *reinterpret_cast<uint32_t*>(g_Aqs + (size_t)row * KK + gi * 4) = pk;
    }
    // metadata, PTX layout for mma.sp 16-bit m16n8k32 (selector 0):
    // per 16-row x 32-k chunk: lane = g*4+t; word bits[0:16) = row g, k-half (t&1)
    // (4 ascending nibbles), bits[16:32) = row g+8 same k-half; lanes t=2,3 duplicate t=0,1.
    const int rb = row >> 4, g = row & 7, hi = (row >> 3) & 1;
#pragma unroll
    for (int j = 0; j < 4; j++) {
        int task = tid * 4 + j;                 // 0..511 = 128 chunks x 2 halves x 2 dups
        int kc = task >> 2, h = task & 1, d = (task >> 1) & 1;
        int g0 = kc * 8 + h * 4;                // first group of this k-half
        uint16_t hw = (uint16_t)(nibs[g0] | (nibs[g0 + 1] << 4) |
                                 (nibs[g0 + 2] << 8) | (nibs[g0 + 3] << 12));
        size_t waddr = (((size_t)rb * 128 + kc) * 32 + g * 4 + d * 2 + h) * 4 + 2 * hi;
        *reinterpret_cast<uint16_t*>(g_Am + waddr) = hw;
    }
}

// ---------------- GEMM: 128x128 CTA tile, 256 threads, sparse bf16 mma.sp ----------------
__global__ void __launch_bounds__(256, 1) gemm_kernel(float* __restrict__ out) {
    extern __shared__ uint8_t dynsm[];
    uint8_t* base = (uint8_t*)(((uintptr_t)dynsm + 1023) & ~(uintptr_t)1023);
    const uint32_t sbase = smem_u32(base);
    const int tid = threadIdx.x, wid = tid >> 5, lane = tid & 31;
    const int mt = blockIdx.x >> 5, nt = blockIdx.x & 31;
    const int m0 = mt * 128, n0g = nt * 128;

    const int wm = wid & 3, wn = wid >> 2;   // warp tile: 32(M) x 64(N)

    float acc[2][8][4];
#pragma unroll
    for (int i = 0; i < 2; i++)
#pragma unroll
        for (int j = 0; j < 8; j++)
#pragma unroll
            for (int k = 0; k < 4; k++) acc[i][j][k] = 0.f;

    // copies per stage (64 logical k): A compressed 128x64B, meta 2KB, B 128x128B
    const int arow = tid >> 1, aoff = (tid & 1) * 32;
    const int crow = tid >> 1, coff = (tid & 1) * 64;
    const int mrb = tid >> 5, moff = (tid & 31) * 8;   // 8B per thread, 256B per rb
    auto copy_stage = [&](int s, int c) {
        uint32_t st = sbase + s * STAGE_BYTES;
        // A (compressed bf16): chunk c -> stored bytes [c*64, c*64+64) of row
        const uint8_t* ga = g_Aqs + (size_t)(m0 + arow) * KK + c * 64 + aoff;
        cp_async16(st + arow * A_STRIDE + aoff, ga);
        cp_async16(st + arow * A_STRIDE + aoff + 16, ga + 16);
        // metadata: rb = mt*8+mrb, k32 chunks c*2, c*2+1 = 256 contiguous bytes
        const uint8_t* gm = g_Am + ((size_t)(mt * 8 + mrb) * 128 + c * 2) * 128 + moff;
        cp_async8(st + SMA + mrb * 256 + moff, gm);
        // B (dense bf16): chunk c -> bytes [c*128, c*128+128) of row
        const uint8_t* gb = (const uint8_t*)(g_Bq + (size_t)(n0g + crow) * KK) + c * 128 + coff;
#pragma unroll
        for (int i = 0; i < 4; i++)
            cp_async16(st + SMA + SMMETA + crow * B_STRIDE + coff + i * 16, gb + i * 16);
        cp_commit();
    };

    copy_stage(0, 0); copy_stage(1, 1);

    const int lr = lane & 15;
    const int lc8 = (lane >> 4) & 1;

    int s = 0;
    for (int c = 0; c < NKC; c++) {
        if (c + 2 < NKC) copy_stage((s + 2) % NSTAGES, c + 2);
        const int rem = NKC - 1 - c;
        if (rem >= 2) cp_wait<2>();
        else if (rem == 1) cp_wait<1>();
        else cp_wait<0>();
        __syncthreads();

        const uint32_t abase = sbase + s * STAGE_BYTES;
        const uint32_t mbase = abase + SMA;
        const uint32_t bbase = mbase + SMMETA;
#pragma unroll
        for (int kb = 0; kb < 2; kb++) {       // two k32 chunks per stage
            uint32_t a[2][4];
            uint32_t e[2];
#pragma unroll
            for (int mi = 0; mi < 2; mi++) {
                int row = wm * 32 + mi * 16 + lr;
                LDSM_X4(a[mi], abase + row * A_STRIDE + kb * 32 + lc8 * 16);
                asm volatile("ld.shared.b32 %0, [%1];"
                    : "=r"(e[mi])
                    : "r"(mbase + (uint32_t)((wm * 2 + mi) * 256 + kb * 128 + lane * 4)));
            }
#pragma unroll
            for (int nb = 0; nb < 4; nb++) {
                int row = wn * 64 + nb * 16 + lr;
                uint32_t B1[4], B2[4];
                LDSM_X4(B1, bbase + row * B_STRIDE + kb * 64 + lc8 * 16);
                LDSM_X4(B2, bbase + row * B_STRIDE + kb * 64 + 32 + lc8 * 16);
#pragma unroll
                for (int mi = 0; mi < 2; mi++) {
                    mma_sp(acc[mi][2 * nb + 0], a[mi], B1[0], B1[2], B2[0], B2[2], e[mi]);
                    mma_sp(acc[mi][2 * nb + 1], a[mi], B1[1], B1[3], B2[1], B2[3], e[mi]);
                }
            }
        }
        __syncthreads();
        s = (s + 1) % NSTAGES;
    }

    // epilogue: apply Xs[m] * Ws[n], round to bf16, store as FLOAT32
    const int wm0 = m0 + wm * 32;
    const int wn0 = n0g + wn * 64;
#pragma unroll
    for (int mi = 0; mi < 2; mi++) {
#pragma unroll
        for (int half = 0; half < 2; half++) {
            int r = wm0 + mi * 16 + (lane >> 2) + half * 8;
            float xs = __ldg(&g_Xs[r]);
            float* orow = out + (size_t)r * NN;
#pragma unroll
            for (int nb8 = 0; nb8 < 8; nb8++) {
                int n = wn0 + nb8 * 8 + (lane & 3) * 2;
                float w0 = __ldg(&g_Ws[n]), w1 = __ldg(&g_Ws[n + 1]);
                float2 o;
                o.x = bf16r(acc[mi][nb8][half * 2 + 0] * xs * w0);
                o.y = bf16r(acc[mi][nb8][half * 2 + 1] * xs * w1);
                *reinterpret_cast<float2*>(orow + n) = o;
            }
        }
    }
}

extern "C" void kernel_launch(void* const* d_in, const int* in_sizes, int n_in,
                              void* d_out, int out_size) {
    // Select inputs by element count — robust to metadata ordering.
    const float* x = (const float*)d_in[0];
    const float* W = (const float*)d_in[1];
    if (n_in >= 2 && in_sizes[0] == NN * KK && in_sizes[1] == MM * KK) {
        x = (const float*)d_in[1];
        W = (const float*)d_in[0];
    }
    float* out = (float*)d_out;     // __output__ dtype is float32
    (void)out_size;

    cudaFuncSetAttribute(gemm_kernel, cudaFuncAttributeMaxDynamicSharedMemorySize, GEMM_SMEM);

    wprep_kernel<<<NN, 128>>>(W);
    xprep_kernel<<<MM, 128>>>(x);
    gemm_kernel<<<(MM / 128) * (NN / 128), 256, GEMM_SMEM>>>(out);
}